// round 1
// baseline (speedup 1.0000x reference)
#include <cuda_runtime.h>
#include <cuda_bf16.h>

// Problem constants
#define Gc    16
#define Kt    5
#define IPG   64
#define OPG   64
#define Lr    4096
#define Br    4
#define KD    (Kt * IPG)          // 320
#define TILE_L 64
#define XS_STRIDE 324             // 320 padded: keeps %4==0 (float4) and 4*324%32==16 (bank split)

#define SMEM_FLOATS (TILE_L * XS_STRIDE + KD * OPG)
#define SMEM_BYTES  (SMEM_FLOATS * 4)   // 82944 + 81920 = 164864 B

// One-time (per launch) transposed weights: [g][kdim][o], kdim = k*IPG + i
__device__ float g_wt[Gc * KD * OPG];

// kernel input layout: [G][OPG][IPG][Kt], flat idx = ((g*OPG + o)*IPG + i)*Kt + k
__global__ void transpose_w_kernel(const float* __restrict__ w) {
    int idx = blockIdx.x * blockDim.x + threadIdx.x;
    const int total = Gc * OPG * IPG * Kt;
    if (idx >= total) return;
    int k = idx % Kt;
    int i = (idx / Kt) % IPG;
    int o = (idx / (Kt * IPG)) % OPG;
    int g = idx / (Kt * IPG * OPG);
    g_wt[((size_t)g * KD + k * IPG + i) * OPG + o] = w[idx];
}

__global__ __launch_bounds__(256, 1)
void masked_conv_kernel(const float* __restrict__ inp,
                        const int* __restrict__ pos,
                        float* __restrict__ out) {
    extern __shared__ float smem[];
    float* Xs = smem;                         // [TILE_L][XS_STRIDE]
    float* Ws = smem + TILE_L * XS_STRIDE;    // [KD][OPG]

    const int g  = blockIdx.y;
    const int b  = blockIdx.z;
    const int l0 = blockIdx.x * TILE_L;
    const int tid = threadIdx.x;

    // ---- Load W tile: fully coalesced float4 copy from pre-transposed weights ----
    {
        const float4* wsrc = (const float4*)(g_wt + (size_t)g * KD * OPG);
        float4* wdst = (float4*)Ws;
        #pragma unroll
        for (int it = 0; it < (KD * OPG / 4) / 256; it++) {   // 20 iters
            wdst[tid + it * 256] = wsrc[tid + it * 256];
        }
    }

    // ---- Load masked X patch: 64 pos x 5 taps x 64 ch, float4 granularity ----
    {
        const int* posb = pos + (size_t)b * Lr;
        #pragma unroll
        for (int it = 0; it < (TILE_L * Kt * (IPG / 4)) / 256; it++) {  // 20 iters
            int e  = tid + it * 256;
            int i4 = e & 15;          // which float4 within the 64-ch group
            int pk = e >> 4;
            int k  = pk % Kt;
            int p  = pk / Kt;
            int l  = l0 + p;
            int ls = l + k - 2;
            float4 v = make_float4(0.f, 0.f, 0.f, 0.f);
            if (ls >= 0 && ls < Lr && posb[ls] == posb[l] + (k - 2)) {
                v = *(const float4*)(inp + ((size_t)b * Lr + ls) * 1024 + g * IPG + i4 * 4);
            }
            *(float4*)(Xs + p * XS_STRIDE + k * IPG + i4 * 4) = v;
        }
    }
    __syncthreads();

    // ---- Compute: 64x64 tile, 4x4 register micro-tile per thread, K = 320 ----
    const int tx = tid & 15;   // output-channel group
    const int ty = tid >> 4;   // position group

    float acc[4][4];
    #pragma unroll
    for (int r = 0; r < 4; r++)
        #pragma unroll
        for (int c = 0; c < 4; c++) acc[r][c] = 0.f;

    const float* xbase = Xs + (ty * 4) * XS_STRIDE;
    const float* wbase = Ws + tx * 4;

#define MAD(r, av, bj)                    \
    acc[r][0] += (av) * (bj).x;           \
    acc[r][1] += (av) * (bj).y;           \
    acc[r][2] += (av) * (bj).z;           \
    acc[r][3] += (av) * (bj).w;

    #pragma unroll 4
    for (int kk = 0; kk < KD; kk += 4) {
        float4 a0 = *(const float4*)(xbase + 0 * XS_STRIDE + kk);
        float4 a1 = *(const float4*)(xbase + 1 * XS_STRIDE + kk);
        float4 a2 = *(const float4*)(xbase + 2 * XS_STRIDE + kk);
        float4 a3 = *(const float4*)(xbase + 3 * XS_STRIDE + kk);
        float4 b0 = *(const float4*)(wbase + (kk + 0) * OPG);
        float4 b1 = *(const float4*)(wbase + (kk + 1) * OPG);
        float4 b2 = *(const float4*)(wbase + (kk + 2) * OPG);
        float4 b3 = *(const float4*)(wbase + (kk + 3) * OPG);

        MAD(0, a0.x, b0) MAD(0, a0.y, b1) MAD(0, a0.z, b2) MAD(0, a0.w, b3)
        MAD(1, a1.x, b0) MAD(1, a1.y, b1) MAD(1, a1.z, b2) MAD(1, a1.w, b3)
        MAD(2, a2.x, b0) MAD(2, a2.y, b1) MAD(2, a2.z, b2) MAD(2, a2.w, b3)
        MAD(3, a3.x, b0) MAD(3, a3.y, b1) MAD(3, a3.z, b2) MAD(3, a3.w, b3)
    }
#undef MAD

    // ---- Store: out[b][l][g][o] ----
    size_t obase = (((size_t)b * Lr + l0 + ty * 4) * Gc + g) * OPG + tx * 4;
    #pragma unroll
    for (int r = 0; r < 4; r++) {
        *(float4*)(out + obase + (size_t)r * Gc * OPG) =
            make_float4(acc[r][0], acc[r][1], acc[r][2], acc[r][3]);
    }
}

extern "C" void kernel_launch(void* const* d_in, const int* in_sizes, int n_in,
                              void* d_out, int out_size) {
    const float* inp = (const float*)d_in[0];   // (4, 4096, 1024) f32
    const int*   pos = (const int*)d_in[1];     // (4, 4096) i32
    const float* w   = (const float*)d_in[2];   // (16, 64, 64, 5) f32
    float* out = (float*)d_out;                 // (4, 4096, 16, 64) f32

    cudaFuncSetAttribute(masked_conv_kernel,
                         cudaFuncAttributeMaxDynamicSharedMemorySize, SMEM_BYTES);

    {
        const int total = Gc * OPG * IPG * Kt;
        transpose_w_kernel<<<(total + 255) / 256, 256>>>(w);
    }

    dim3 grid(Lr / TILE_L, Gc, Br);  // (64, 16, 4)
    masked_conv_kernel<<<grid, 256, SMEM_BYTES>>>(inp, pos, out);
}

// round 3
// speedup vs baseline: 3.8517x; 3.8517x over previous
#include <cuda_runtime.h>
#include <cuda_bf16.h>
#include <cstdint>

// ---------------- problem constants ----------------
#define Gc    16
#define Kt    5
#define IPG   64
#define OPG   64
#define Lr    4096
#define Br    4
#define TILE_M 128
#define XROWS  (TILE_M + 4)     // 132 rows incl. +/-2 halo
#define XSTRIDE 144             // bytes/row: 128 data + 16 pad (conflict-free ldmatrix)

// ---------------- smem layout (bytes) ----------------
#define SM_MASK 0                                 // 5*128*4   = 2560
#define SM_XH   2560                              // 132*144   = 19008
#define SM_XL   (SM_XH + XROWS * XSTRIDE)         // 21568
#define SM_WS   (SM_XL + XROWS * XSTRIDE)         // 40576 ; W frags 81920
#define SM_TOTAL (SM_WS + 81920)                  // 122496

// ---------------- W fragment scratch ----------------
// layout: [g][term(2)][tap(5)][kc(4)][o(64)][q(4)] as uint2 (b0,b1 regs of mma B frag)
// per g: 2*5*4*64*4 = 10240 uint2 = 81920 B
__device__ uint2 g_wfrag[Gc * 10240];

__device__ __forceinline__ uint32_t pack_bf2(__nv_bfloat16 lo, __nv_bfloat16 hi) {
    return (uint32_t)__bfloat16_as_ushort(lo) | ((uint32_t)__bfloat16_as_ushort(hi) << 16);
}
__device__ __forceinline__ void split1(float v, __nv_bfloat16& h, __nv_bfloat16& l) {
    h = __float2bfloat16(v);
    l = __float2bfloat16(v - __bfloat162float(h));
}

// w input layout: w[g][o][i][k], flat = ((g*64+o)*64+i)*5+k
__global__ void build_wfrag_kernel(const float* __restrict__ w) {
    int idx = blockIdx.x * blockDim.x + threadIdx.x;
    if (idx >= Gc * 5120) return;
    int g    = idx / 5120;
    int rem  = idx % 5120;
    int tap  = rem / 1024;
    int rem2 = rem % 1024;
    int kc   = rem2 >> 8;
    int o    = (rem2 >> 2) & 63;
    int q    = rem2 & 3;
    int i0 = kc * 16 + q * 2;

    const float* wb = w + (((size_t)g * OPG + o) * IPG) * Kt + tap;
    float v0 = wb[(i0 + 0) * Kt], v1 = wb[(i0 + 1) * Kt];
    float v2 = wb[(i0 + 8) * Kt], v3 = wb[(i0 + 9) * Kt];

    __nv_bfloat16 h0, h1, h2, h3, l0, l1, l2, l3;
    split1(v0, h0, l0); split1(v1, h1, l1);
    split1(v2, h2, l2); split1(v3, h3, l3);

    uint2* base = g_wfrag + (size_t)g * 10240;
    int sub = ((tap * 4 + kc) << 8) + (o * 4 + q);
    base[sub]        = make_uint2(pack_bf2(h0, h1), pack_bf2(h2, h3));   // term hi
    base[5120 + sub] = make_uint2(pack_bf2(l0, l1), pack_bf2(l2, l3));   // term lo
}

// ---------------- ptx helpers ----------------
__device__ __forceinline__ uint32_t smem_u32(const void* p) {
    uint32_t a;
    asm("{ .reg .u64 t; cvta.to.shared.u64 t, %1; cvt.u32.u64 %0, t; }" : "=r"(a) : "l"(p));
    return a;
}
__device__ __forceinline__ void ldsm4(uint32_t (&r)[4], uint32_t addr) {
    asm volatile("ldmatrix.sync.aligned.m8n8.x4.shared.b16 {%0,%1,%2,%3}, [%4];"
                 : "=r"(r[0]), "=r"(r[1]), "=r"(r[2]), "=r"(r[3]) : "r"(addr));
}
__device__ __forceinline__ void mma16816(float (&d)[4], const uint32_t (&a)[4],
                                         uint32_t b0, uint32_t b1) {
    asm volatile("mma.sync.aligned.m16n8k16.row.col.f32.bf16.bf16.f32 "
                 "{%0,%1,%2,%3}, {%4,%5,%6,%7}, {%8,%9}, {%0,%1,%2,%3};"
                 : "+f"(d[0]), "+f"(d[1]), "+f"(d[2]), "+f"(d[3])
                 : "r"(a[0]), "r"(a[1]), "r"(a[2]), "r"(a[3]), "r"(b0), "r"(b1));
}

// ---------------- main kernel ----------------
__global__ __launch_bounds__(256, 1)
void conv_hmma_kernel(const float* __restrict__ inp,
                      const int* __restrict__ pos,
                      float* __restrict__ out) {
    extern __shared__ char smem[];
    const int tid = threadIdx.x;
    const int lam = tid & 31, wid = tid >> 5;
    const int wm = wid & 3, wn = wid >> 2;          // warp grid 4(m) x 2(n)
    const int g = blockIdx.y, b = blockIdx.z;
    const int lt = blockIdx.x * TILE_M;
    const int* posb = pos + (size_t)b * Lr;

    // ---- stage W fragments for this g into smem (coalesced 128b copies) ----
    {
        const uint4* wsrc = (const uint4*)g_wfrag + (size_t)g * 5120;
        uint4* wdst = (uint4*)(smem + SM_WS);
        #pragma unroll
        for (int it = 0; it < 20; it++)
            wdst[tid + it * 256] = wsrc[tid + it * 256];
    }

    // ---- mask table: mask[tap][m] ----
    {
        float* mk = (float*)(smem + SM_MASK);
        for (int e = tid; e < Kt * TILE_M; e += 256) {
            int tap = e >> 7, m = e & 127;
            int l = lt + m, ls = l + tap - 2;
            float v = 0.f;
            if (ls >= 0 && ls < Lr && __ldg(posb + ls) == __ldg(posb + l) + (tap - 2))
                v = 1.f;
            mk[tap * TILE_M + m] = v;
        }
    }

    // ---- convert X rows [lt-2, lt+130) x 64ch to bf16 hi/lo, once ----
    for (int e = tid; e < XROWS * 16; e += 256) {
        int c4 = e & 15, r = e >> 4;
        int gl = lt - 2 + r;
        float4 v = make_float4(0.f, 0.f, 0.f, 0.f);
        if (gl >= 0 && gl < Lr)
            v = __ldg((const float4*)(inp + ((size_t)b * Lr + gl) * 1024 + g * IPG) + c4);

        __nv_bfloat162 h01 = __float22bfloat162_rn(make_float2(v.x, v.y));
        __nv_bfloat162 h23 = __float22bfloat162_rn(make_float2(v.z, v.w));
        float r0 = v.x - __low2float(h01), r1 = v.y - __high2float(h01);
        float r2 = v.z - __low2float(h23), r3 = v.w - __high2float(h23);
        __nv_bfloat162 l01 = __float22bfloat162_rn(make_float2(r0, r1));
        __nv_bfloat162 l23 = __float22bfloat162_rn(make_float2(r2, r3));

        uint32_t off = r * XSTRIDE + c4 * 8;
        *(uint2*)(smem + SM_XH + off) =
            make_uint2(*(uint32_t*)&h01, *(uint32_t*)&h23);
        *(uint2*)(smem + SM_XL + off) =
            make_uint2(*(uint32_t*)&l01, *(uint32_t*)&l23);
    }
    __syncthreads();

    // ---- mainloop ----
    const uint32_t sb = smem_u32(smem);
    const uint32_t xh_base = sb + SM_XH, xl_base = sb + SM_XL;
    // ldmatrix lane address: lanes 0-15 -> rows 0-15, lanes 16-31 -> same rows, +16B col
    const uint32_t a_off = (uint32_t)((wm * 32 + (lam & 15)) * XSTRIDE + (lam >> 4) * 16);
    const uint2* wsm = (const uint2*)(smem + SM_WS);
    const int bq = (wn * 32 + (lam >> 2)) * 4 + (lam & 3);   // B frag lane index base

    float facc[2][4][4];
    #pragma unroll
    for (int mi = 0; mi < 2; mi++)
        #pragma unroll
        for (int nj = 0; nj < 4; nj++)
            #pragma unroll
            for (int c = 0; c < 4; c++) facc[mi][nj][c] = 0.f;

    for (int tap = 0; tap < Kt; tap++) {
        float y[2][4][4];
        #pragma unroll
        for (int mi = 0; mi < 2; mi++)
            #pragma unroll
            for (int nj = 0; nj < 4; nj++)
                #pragma unroll
                for (int c = 0; c < 4; c++) y[mi][nj][c] = 0.f;

        #pragma unroll
        for (int ks = 0; ks < 4; ks++) {
            uint32_t ao = a_off + tap * XSTRIDE + ks * 32;
            uint32_t ah0[4], ah1[4], al0[4], al1[4];
            ldsm4(ah0, xh_base + ao);
            ldsm4(ah1, xh_base + ao + 16 * XSTRIDE);
            ldsm4(al0, xl_base + ao);
            ldsm4(al1, xl_base + ao + 16 * XSTRIDE);

            #pragma unroll
            for (int nj = 0; nj < 4; nj++) {
                uint2 bh = wsm[(tap * 4 + ks) * 256 + bq + nj * 32];
                uint2 bl = wsm[((5 + tap) * 4 + ks) * 256 + bq + nj * 32];
                mma16816(y[0][nj], ah0, bh.x, bh.y);
                mma16816(y[1][nj], ah1, bh.x, bh.y);
                mma16816(y[0][nj], ah0, bl.x, bl.y);
                mma16816(y[1][nj], ah1, bl.x, bl.y);
                mma16816(y[0][nj], al0, bh.x, bh.y);
                mma16816(y[1][nj], al1, bh.x, bh.y);
            }
        }

        // per-row scalar mask fold: facc += mask * y
        const float* mrow = (const float*)(smem + SM_MASK) + tap * TILE_M + wm * 32;
        #pragma unroll
        for (int mi = 0; mi < 2; mi++) {
            float mk0 = mrow[mi * 16 + (lam >> 2)];
            float mk1 = mrow[mi * 16 + (lam >> 2) + 8];
            #pragma unroll
            for (int nj = 0; nj < 4; nj++) {
                facc[mi][nj][0] += mk0 * y[mi][nj][0];
                facc[mi][nj][1] += mk0 * y[mi][nj][1];
                facc[mi][nj][2] += mk1 * y[mi][nj][2];
                facc[mi][nj][3] += mk1 * y[mi][nj][3];
            }
        }
    }

    // ---- epilogue: out[b][l][g][o] ----
    #pragma unroll
    for (int mi = 0; mi < 2; mi++) {
        int row0 = wm * 32 + mi * 16 + (lam >> 2);
        #pragma unroll
        for (int nj = 0; nj < 4; nj++) {
            int col = wn * 32 + nj * 8 + (lam & 3) * 2;
            size_t base = (((size_t)b * Lr + lt + row0) * Gc + g) * OPG + col;
            *(float2*)(out + base) = make_float2(facc[mi][nj][0], facc[mi][nj][1]);
            *(float2*)(out + base + (size_t)8 * Gc * OPG) =
                make_float2(facc[mi][nj][2], facc[mi][nj][3]);
        }
    }
}

extern "C" void kernel_launch(void* const* d_in, const int* in_sizes, int n_in,
                              void* d_out, int out_size) {
    const float* inp = (const float*)d_in[0];   // (4, 4096, 1024) f32
    const int*   pos = (const int*)d_in[1];     // (4, 4096) i32
    const float* w   = (const float*)d_in[2];   // (16, 64, 64, 5) f32
    float* out = (float*)d_out;                 // (4, 4096, 16, 64) f32

    build_wfrag_kernel<<<(Gc * 5120 + 255) / 256, 256>>>(w);

    cudaFuncSetAttribute(conv_hmma_kernel,
                         cudaFuncAttributeMaxDynamicSharedMemorySize, SM_TOTAL);
    dim3 grid(Lr / TILE_M, Gc, Br);   // (32, 16, 4)
    conv_hmma_kernel<<<grid, 256, SM_TOTAL>>>(inp, pos, out);
}

// round 4
// speedup vs baseline: 3.9834x; 1.0342x over previous
#include <cuda_runtime.h>
#include <cuda_bf16.h>
#include <cstdint>

// ---------------- problem constants ----------------
#define Gc    16
#define Kt    5
#define IPG   64
#define OPG   64
#define Lr    4096
#define Br    4
#define TILE_M 128
#define XROWS  (TILE_M + 4)     // 132 rows incl. +/-2 halo

// ---------------- smem layout (bytes) ----------------
// X tiles: XOR-swizzled, 128B per row (64 bf16)
#define SM_XH   0                                  // 132*128 = 16896
#define SM_XL   16896                              // 16896
#define SM_W    33792                              // 81920 (5120 uint4)
#define SM_POS  115712                             // 136 ints = 544
#define SM_ZERO 116256                             // 128B zero block
#define SM_TOTAL 116384

// ---------------- W fragment scratch ----------------
// [g][tap][kc][o][q] uint4 = {bh0,bh1,bl0,bl1}; per g: 5*4*64*4 = 5120 uint4
__device__ uint4 g_wfrag[Gc * 5120];

__device__ __forceinline__ uint32_t pack_bf2(__nv_bfloat16 lo, __nv_bfloat16 hi) {
    return (uint32_t)__bfloat16_as_ushort(lo) | ((uint32_t)__bfloat16_as_ushort(hi) << 16);
}
__device__ __forceinline__ void split1(float v, __nv_bfloat16& h, __nv_bfloat16& l) {
    h = __float2bfloat16(v);
    l = __float2bfloat16(v - __bfloat162float(h));
}

// w input layout: w[g][o][i][k], flat = ((g*64+o)*64+i)*5+k
__global__ void build_wfrag_kernel(const float* __restrict__ w) {
    int idx = blockIdx.x * blockDim.x + threadIdx.x;
    if (idx >= Gc * 5120) return;
    int g    = idx / 5120;
    int rem  = idx % 5120;
    int tap  = rem / 1024;
    int rem2 = rem % 1024;
    int kc   = rem2 >> 8;
    int o    = (rem2 >> 2) & 63;
    int q    = rem2 & 3;
    int i0 = kc * 16 + q * 2;

    const float* wb = w + (((size_t)g * OPG + o) * IPG) * Kt + tap;
    float v0 = wb[(i0 + 0) * Kt], v1 = wb[(i0 + 1) * Kt];
    float v2 = wb[(i0 + 8) * Kt], v3 = wb[(i0 + 9) * Kt];

    __nv_bfloat16 h0, h1, h2, h3, l0, l1, l2, l3;
    split1(v0, h0, l0); split1(v1, h1, l1);
    split1(v2, h2, l2); split1(v3, h3, l3);

    uint4 out;
    out.x = pack_bf2(h0, h1); out.y = pack_bf2(h2, h3);
    out.z = pack_bf2(l0, l1); out.w = pack_bf2(l2, l3);
    g_wfrag[(size_t)g * 5120 + ((tap * 4 + kc) << 8) + (o * 4 + q)] = out;
}

// ---------------- ptx helpers ----------------
__device__ __forceinline__ uint32_t smem_u32(const void* p) {
    uint32_t a;
    asm("{ .reg .u64 t; cvta.to.shared.u64 t, %1; cvt.u32.u64 %0, t; }" : "=r"(a) : "l"(p));
    return a;
}
__device__ __forceinline__ void ldsm4(uint32_t (&r)[4], uint32_t addr) {
    asm volatile("ldmatrix.sync.aligned.m8n8.x4.shared.b16 {%0,%1,%2,%3}, [%4];"
                 : "=r"(r[0]), "=r"(r[1]), "=r"(r[2]), "=r"(r[3]) : "r"(addr));
}
__device__ __forceinline__ void mma16816(float (&d)[4], const uint32_t (&a)[4],
                                         uint32_t b0, uint32_t b1) {
    asm volatile("mma.sync.aligned.m16n8k16.row.col.f32.bf16.bf16.f32 "
                 "{%0,%1,%2,%3}, {%4,%5,%6,%7}, {%8,%9}, {%0,%1,%2,%3};"
                 : "+f"(d[0]), "+f"(d[1]), "+f"(d[2]), "+f"(d[3])
                 : "r"(a[0]), "r"(a[1]), "r"(a[2]), "r"(a[3]), "r"(b0), "r"(b1));
}

// ---------------- main kernel ----------------
__global__ __launch_bounds__(256, 2)
void conv_hmma_kernel(const float* __restrict__ inp,
                      const int* __restrict__ pos,
                      float* __restrict__ out) {
    extern __shared__ char smem[];
    const int tid = threadIdx.x;
    const int lam = tid & 31, wid = tid >> 5;
    const int wm = wid & 3, wn = wid >> 2;          // warp grid 4(m) x 2(n)
    const int g = blockIdx.y, b = blockIdx.z;
    const int lt = blockIdx.x * TILE_M;
    const int* posb = pos + (size_t)b * Lr;

    // ---- stage W fragments (uint4 interleaved hi/lo) ----
    {
        const uint4* wsrc = g_wfrag + (size_t)g * 5120;
        uint4* wdst = (uint4*)(smem + SM_W);
        #pragma unroll
        for (int it = 0; it < 20; it++)
            wdst[tid + it * 256] = wsrc[tid + it * 256];
    }

    // ---- stage pos rows [lt-2, lt+130) with OOB sentinel; zero block ----
    {
        int* poss = (int*)(smem + SM_POS);
        if (tid < XROWS) {
            int gl = lt - 2 + tid;
            poss[tid] = (gl >= 0 && gl < Lr) ? __ldg(posb + gl) : -100000;
        }
        if (tid < 8) ((uint4*)(smem + SM_ZERO))[tid & 7] = make_uint4(0, 0, 0, 0);
    }

    // ---- convert X rows to bf16 hi/lo, swizzled 128B rows ----
    for (int e = tid; e < XROWS * 16; e += 256) {
        int c4 = e & 15, r = e >> 4;               // c4: 8B slot 0..15
        int gl = lt - 2 + r;
        float4 v = make_float4(0.f, 0.f, 0.f, 0.f);
        if (gl >= 0 && gl < Lr)
            v = __ldg((const float4*)(inp + ((size_t)b * Lr + gl) * 1024 + g * IPG) + c4);

        __nv_bfloat162 h01 = __float22bfloat162_rn(make_float2(v.x, v.y));
        __nv_bfloat162 h23 = __float22bfloat162_rn(make_float2(v.z, v.w));
        float r0 = v.x - __low2float(h01), r1 = v.y - __high2float(h01);
        float r2 = v.z - __low2float(h23), r3 = v.w - __high2float(h23);
        __nv_bfloat162 l01 = __float22bfloat162_rn(make_float2(r0, r1));
        __nv_bfloat162 l23 = __float22bfloat162_rn(make_float2(r2, r3));

        uint32_t off = r * 128 + (((c4 >> 1) ^ (r & 7)) << 4) + (c4 & 1) * 8;
        *(uint2*)(smem + SM_XH + off) = make_uint2(*(uint32_t*)&h01, *(uint32_t*)&h23);
        *(uint2*)(smem + SM_XL + off) = make_uint2(*(uint32_t*)&l01, *(uint32_t*)&l23);
    }
    __syncthreads();

    // ---- precompute per-lane ldsm base addresses with mask redirect ----
    const uint32_t sb = smem_u32(smem);
    const uint32_t zeroblk = sb + SM_ZERO;
    const int arow = lam & 15;                      // ldsm address row within 16-block
    const uint32_t hi16 = (lam >> 4) << 4;          // 0 or 16: col-half byte offset
    const int* poss = (const int*)(smem + SM_POS);

    uint32_t baseH[Kt][2], baseL[Kt][2];
    uint32_t r7[Kt];
    #pragma unroll
    for (int tap = 0; tap < Kt; tap++) {
        r7[tap] = (uint32_t)((arow + tap) & 7);
        #pragma unroll
        for (int mi = 0; mi < 2; mi++) {
            int row_m = wm * 32 + mi * 16 + arow;   // A row 0..127
            int xrow  = row_m + tap;                // X row 0..131
            int l = lt + row_m, ls = l + tap - 2;
            bool valid = (ls >= 0 && ls < Lr) &&
                         (poss[xrow] == poss[row_m + 2] + (tap - 2));
            baseH[tap][mi] = valid ? (sb + SM_XH + xrow * 128) : zeroblk;
            baseL[tap][mi] = valid ? (sb + SM_XL + xrow * 128) : zeroblk;
        }
    }

    const uint4* wsm = (const uint4*)(smem + SM_W);
    const int bq = (wn * 32 + (lam >> 2)) * 4 + (lam & 3);

    float facc[2][4][4];
    #pragma unroll
    for (int mi = 0; mi < 2; mi++)
        #pragma unroll
        for (int nj = 0; nj < 4; nj++)
            #pragma unroll
            for (int c = 0; c < 4; c++) facc[mi][nj][c] = 0.f;

    // ---- mainloop: 5 taps x 4 k-steps x (8 MMA-slots x 3 terms) ----
    #pragma unroll
    for (int tap = 0; tap < Kt; tap++) {
        #pragma unroll
        for (int ks = 0; ks < 4; ks++) {
            uint32_t swz = ((((uint32_t)(ks * 2) + (lam >> 4)) ^ r7[tap]) << 4);
            uint32_t ah0[4], ah1[4], al0[4], al1[4];
            ldsm4(ah0, baseH[tap][0] + swz);
            ldsm4(ah1, baseH[tap][1] + swz);
            ldsm4(al0, baseL[tap][0] + swz);
            ldsm4(al1, baseL[tap][1] + swz);

            #pragma unroll
            for (int nj = 0; nj < 4; nj++) {
                uint4 bb = wsm[(tap * 4 + ks) * 256 + bq + nj * 32];
                mma16816(facc[0][nj], ah0, bb.x, bb.y);   // Ah*Bh
                mma16816(facc[1][nj], ah1, bb.x, bb.y);
                mma16816(facc[0][nj], ah0, bb.z, bb.w);   // Ah*Bl
                mma16816(facc[1][nj], ah1, bb.z, bb.w);
                mma16816(facc[0][nj], al0, bb.x, bb.y);   // Al*Bh
                mma16816(facc[1][nj], al1, bb.x, bb.y);
            }
        }
    }

    // ---- epilogue: out[b][l][g][o] ----
    #pragma unroll
    for (int mi = 0; mi < 2; mi++) {
        int row0 = wm * 32 + mi * 16 + (lam >> 2);
        #pragma unroll
        for (int nj = 0; nj < 4; nj++) {
            int col = wn * 32 + nj * 8 + (lam & 3) * 2;
            size_t base = (((size_t)b * Lr + lt + row0) * Gc + g) * OPG + col;
            *(float2*)(out + base) = make_float2(facc[mi][nj][0], facc[mi][nj][1]);
            *(float2*)(out + base + (size_t)8 * Gc * OPG) =
                make_float2(facc[mi][nj][2], facc[mi][nj][3]);
        }
    }
}

extern "C" void kernel_launch(void* const* d_in, const int* in_sizes, int n_in,
                              void* d_out, int out_size) {
    const float* inp = (const float*)d_in[0];   // (4, 4096, 1024) f32
    const int*   pos = (const int*)d_in[1];     // (4, 4096) i32
    const float* w   = (const float*)d_in[2];   // (16, 64, 64, 5) f32
    float* out = (float*)d_out;                 // (4, 4096, 16, 64) f32

    build_wfrag_kernel<<<(Gc * 5120 + 255) / 256, 256>>>(w);

    cudaFuncSetAttribute(conv_hmma_kernel,
                         cudaFuncAttributeMaxDynamicSharedMemorySize, SM_TOTAL);
    dim3 grid(Lr / TILE_M, Gc, Br);   // (32, 16, 4)
    conv_hmma_kernel<<<grid, 256, SM_TOTAL>>>(inp, pos, out);
}

// round 5
// speedup vs baseline: 5.5331x; 1.3891x over previous
#include <cuda_runtime.h>
#include <cuda_bf16.h>
#include <cstdint>

// ---------------- problem constants ----------------
#define Gc    16
#define Kt    5
#define IPG   64
#define OPG   64
#define Lr    4096
#define Br    4
#define TILE_M 256
#define XROWS  (TILE_M + 4)     // 260 rows incl. +/-2 halo
#define NTHR   512

// ---------------- smem layout (bytes) ----------------
#define SM_XH   0                                  // 260*128 = 33280
#define SM_XL   33280                              // 33280
#define SM_W    66560                              // 81920 (5120 uint4)
#define SM_POS  148480                             // 260 ints = 1040
#define SM_ZERO 149632                             // 128B zero block (16B aligned)
#define SM_TOTAL 149760

// ---------------- W fragment scratch ----------------
// [g][tap][kc][o][q] uint4 = {bh0,bh1,bl0,bl1}; per g: 5*4*64*4 = 5120 uint4
__device__ uint4 g_wfrag[Gc * 5120];

__device__ __forceinline__ uint32_t pack_bf2(__nv_bfloat16 lo, __nv_bfloat16 hi) {
    return (uint32_t)__bfloat16_as_ushort(lo) | ((uint32_t)__bfloat16_as_ushort(hi) << 16);
}
__device__ __forceinline__ void split1(float v, __nv_bfloat16& h, __nv_bfloat16& l) {
    h = __float2bfloat16(v);
    l = __float2bfloat16(v - __bfloat162float(h));
}

// w input layout: w[g][o][i][k], flat = ((g*64+o)*64+i)*5+k
__global__ void build_wfrag_kernel(const float* __restrict__ w) {
    int idx = blockIdx.x * blockDim.x + threadIdx.x;
    if (idx >= Gc * 5120) return;
    int g    = idx / 5120;
    int rem  = idx % 5120;
    int tap  = rem / 1024;
    int rem2 = rem % 1024;
    int kc   = rem2 >> 8;
    int o    = (rem2 >> 2) & 63;
    int q    = rem2 & 3;
    int i0 = kc * 16 + q * 2;

    const float* wb = w + (((size_t)g * OPG + o) * IPG) * Kt + tap;
    float v0 = wb[(i0 + 0) * Kt], v1 = wb[(i0 + 1) * Kt];
    float v2 = wb[(i0 + 8) * Kt], v3 = wb[(i0 + 9) * Kt];

    __nv_bfloat16 h0, h1, h2, h3, l0, l1, l2, l3;
    split1(v0, h0, l0); split1(v1, h1, l1);
    split1(v2, h2, l2); split1(v3, h3, l3);

    uint4 outv;
    outv.x = pack_bf2(h0, h1); outv.y = pack_bf2(h2, h3);
    outv.z = pack_bf2(l0, l1); outv.w = pack_bf2(l2, l3);
    g_wfrag[(size_t)g * 5120 + ((tap * 4 + kc) << 8) + (o * 4 + q)] = outv;
}

// ---------------- ptx helpers ----------------
__device__ __forceinline__ uint32_t smem_u32(const void* p) {
    uint32_t a;
    asm("{ .reg .u64 t; cvta.to.shared.u64 t, %1; cvt.u32.u64 %0, t; }" : "=r"(a) : "l"(p));
    return a;
}
__device__ __forceinline__ void ldsm4(uint32_t (&r)[4], uint32_t addr) {
    asm volatile("ldmatrix.sync.aligned.m8n8.x4.shared.b16 {%0,%1,%2,%3}, [%4];"
                 : "=r"(r[0]), "=r"(r[1]), "=r"(r[2]), "=r"(r[3]) : "r"(addr));
}
__device__ __forceinline__ void mma16816(float (&d)[4], const uint32_t (&a)[4],
                                         uint32_t b0, uint32_t b1) {
    asm volatile("mma.sync.aligned.m16n8k16.row.col.f32.bf16.bf16.f32 "
                 "{%0,%1,%2,%3}, {%4,%5,%6,%7}, {%8,%9}, {%0,%1,%2,%3};"
                 : "+f"(d[0]), "+f"(d[1]), "+f"(d[2]), "+f"(d[3])
                 : "r"(a[0]), "r"(a[1]), "r"(a[2]), "r"(a[3]), "r"(b0), "r"(b1));
}

// ---------------- main kernel ----------------
__global__ __launch_bounds__(NTHR, 1)
void conv_hmma_kernel(const float* __restrict__ inp,
                      const int* __restrict__ pos,
                      float* __restrict__ out) {
    extern __shared__ char smem[];
    const int tid = threadIdx.x;
    const int lam = tid & 31, wid = tid >> 5;
    const int wm = wid & 7, wn = wid >> 3;          // warp grid 8(m) x 2(n)
    const int g = blockIdx.y, b = blockIdx.z;
    const int lt = blockIdx.x * TILE_M;
    const int* posb = pos + (size_t)b * Lr;

    // ---- stage W fragments (uint4 interleaved hi/lo) ----
    {
        const uint4* wsrc = g_wfrag + (size_t)g * 5120;
        uint4* wdst = (uint4*)(smem + SM_W);
        #pragma unroll
        for (int it = 0; it < 10; it++)
            wdst[tid + it * NTHR] = wsrc[tid + it * NTHR];
    }

    // ---- stage pos rows [lt-2, lt+258) with OOB sentinel; zero block ----
    {
        int* poss = (int*)(smem + SM_POS);
        if (tid < XROWS) {
            int gl = lt - 2 + tid;
            poss[tid] = (gl >= 0 && gl < Lr) ? __ldg(posb + gl) : -100000;
        }
        if (tid < 8) ((uint4*)(smem + SM_ZERO))[tid] = make_uint4(0, 0, 0, 0);
    }

    // ---- convert X rows to bf16 hi/lo, swizzled 128B rows ----
    for (int e = tid; e < XROWS * 16; e += NTHR) {
        int c4 = e & 15, r = e >> 4;
        int gl = lt - 2 + r;
        float4 v = make_float4(0.f, 0.f, 0.f, 0.f);
        if (gl >= 0 && gl < Lr)
            v = __ldg((const float4*)(inp + ((size_t)b * Lr + gl) * 1024 + g * IPG) + c4);

        __nv_bfloat162 h01 = __float22bfloat162_rn(make_float2(v.x, v.y));
        __nv_bfloat162 h23 = __float22bfloat162_rn(make_float2(v.z, v.w));
        float r0 = v.x - __low2float(h01), r1 = v.y - __high2float(h01);
        float r2 = v.z - __low2float(h23), r3 = v.w - __high2float(h23);
        __nv_bfloat162 l01 = __float22bfloat162_rn(make_float2(r0, r1));
        __nv_bfloat162 l23 = __float22bfloat162_rn(make_float2(r2, r3));

        uint32_t off = r * 128 + (((c4 >> 1) ^ (r & 7)) << 4) + (c4 & 1) * 8;
        *(uint2*)(smem + SM_XH + off) = make_uint2(*(uint32_t*)&h01, *(uint32_t*)&h23);
        *(uint2*)(smem + SM_XL + off) = make_uint2(*(uint32_t*)&l01, *(uint32_t*)&l23);
    }
    __syncthreads();

    // ---- precompute per-lane ldsm base addresses with mask redirect ----
    const uint32_t sb = smem_u32(smem);
    const uint32_t zeroblk = sb + SM_ZERO;
    const int arow = lam & 15;
    const int* poss = (const int*)(smem + SM_POS);

    uint32_t baseH[Kt][2], baseL[Kt][2];
    uint32_t r7[Kt];
    #pragma unroll
    for (int tap = 0; tap < Kt; tap++) {
        r7[tap] = (uint32_t)((arow + tap) & 7);
        #pragma unroll
        for (int mi = 0; mi < 2; mi++) {
            int row_m = wm * 32 + mi * 16 + arow;   // A row 0..255
            int xrow  = row_m + tap;                // X row 0..259
            int ls = lt + row_m + tap - 2;
            bool valid = (ls >= 0 && ls < Lr) &&
                         (poss[xrow] == poss[row_m + 2] + (tap - 2));
            baseH[tap][mi] = valid ? (sb + SM_XH + xrow * 128) : zeroblk;
            baseL[tap][mi] = valid ? (sb + SM_XL + xrow * 128) : zeroblk;
        }
    }

    const uint4* wsm = (const uint4*)(smem + SM_W);
    const int bq = (wn * 32 + (lam >> 2)) * 4 + (lam & 3);

    float facc[2][4][4];
    #pragma unroll
    for (int mi = 0; mi < 2; mi++)
        #pragma unroll
        for (int nj = 0; nj < 4; nj++)
            #pragma unroll
            for (int c = 0; c < 4; c++) facc[mi][nj][c] = 0.f;

    // ---- mainloop: 5 taps x 4 k-steps x (8 MMA-slots x 3 terms) ----
    #pragma unroll
    for (int tap = 0; tap < Kt; tap++) {
        #pragma unroll
        for (int ks = 0; ks < 4; ks++) {
            uint32_t swz = ((((uint32_t)(ks * 2) + (lam >> 4)) ^ r7[tap]) << 4);
            uint32_t ah0[4], ah1[4], al0[4], al1[4];
            ldsm4(ah0, baseH[tap][0] + swz);
            ldsm4(ah1, baseH[tap][1] + swz);
            ldsm4(al0, baseL[tap][0] + swz);
            ldsm4(al1, baseL[tap][1] + swz);

            #pragma unroll
            for (int nj = 0; nj < 4; nj++) {
                uint4 bb = wsm[(tap * 4 + ks) * 256 + bq + nj * 32];
                mma16816(facc[0][nj], ah0, bb.x, bb.y);   // Ah*Bh
                mma16816(facc[1][nj], ah1, bb.x, bb.y);
                mma16816(facc[0][nj], ah0, bb.z, bb.w);   // Ah*Bl
                mma16816(facc[1][nj], ah1, bb.z, bb.w);
                mma16816(facc[0][nj], al0, bb.x, bb.y);   // Al*Bh
                mma16816(facc[1][nj], al1, bb.x, bb.y);
            }
        }
    }

    // ---- epilogue: out[b][l][g][o] ----
    #pragma unroll
    for (int mi = 0; mi < 2; mi++) {
        int row0 = wm * 32 + mi * 16 + (lam >> 2);
        #pragma unroll
        for (int nj = 0; nj < 4; nj++) {
            int col = wn * 32 + nj * 8 + (lam & 3) * 2;
            size_t base = (((size_t)b * Lr + lt + row0) * Gc + g) * OPG + col;
            *(float2*)(out + base) = make_float2(facc[mi][nj][0], facc[mi][nj][1]);
            *(float2*)(out + base + (size_t)8 * Gc * OPG) =
                make_float2(facc[mi][nj][2], facc[mi][nj][3]);
        }
    }
}

extern "C" void kernel_launch(void* const* d_in, const int* in_sizes, int n_in,
                              void* d_out, int out_size) {
    const float* inp = (const float*)d_in[0];   // (4, 4096, 1024) f32
    const int*   pos = (const int*)d_in[1];     // (4, 4096) i32
    const float* w   = (const float*)d_in[2];   // (16, 64, 64, 5) f32
    float* out = (float*)d_out;                 // (4, 4096, 16, 64) f32

    build_wfrag_kernel<<<(Gc * 5120 + 255) / 256, 256>>>(w);

    cudaFuncSetAttribute(conv_hmma_kernel,
                         cudaFuncAttributeMaxDynamicSharedMemorySize, SM_TOTAL);
    dim3 grid(Lr / TILE_M, Gc, Br);   // (16, 16, 4)
    conv_hmma_kernel<<<grid, NTHR, SM_TOTAL>>>(inp, pos, out);
}

// round 6
// speedup vs baseline: 11.1410x; 2.0135x over previous
#include <cuda_runtime.h>
#include <cuda_fp16.h>
#include <cstdint>

// ---------------- problem constants ----------------
#define Gc    16
#define Kt    5
#define IPG   64
#define OPG   64
#define Lr    4096
#define Br    4
#define TILE_M 256
#define XROWS  (TILE_M + 4)     // 260 rows incl. +/-2 halo
#define NTHR   512

// ---------------- smem layout (bytes) ----------------
#define SM_XH   0                                  // 260*128 = 33280 (fp16 X, swizzled)
#define SM_W    33280                              // 5120 uint2 = 40960
#define SM_POS  74240                              // 260 ints = 1040
#define SM_ZERO 75392                              // 128B zero block (128B aligned)
#define SM_TOTAL 75520

// ---------------- W fragment scratch ----------------
// [g][tap][kc][o][q] uint2 = {b0,b1} fp16 frags; per g: 5*4*64*4 = 5120 uint2
__device__ uint2 g_wfrag[Gc * 5120];

__device__ __forceinline__ uint32_t pack_h2(__half a, __half b) {
    return (uint32_t)__half_as_ushort(a) | ((uint32_t)__half_as_ushort(b) << 16);
}

// w input layout: w[g][o][i][k], flat = ((g*64+o)*64+i)*5+k
__global__ void build_wfrag_kernel(const float* __restrict__ w) {
    int idx = blockIdx.x * blockDim.x + threadIdx.x;
    if (idx >= Gc * 5120) return;
    int g    = idx / 5120;
    int rem  = idx % 5120;
    int tap  = rem / 1024;
    int rem2 = rem % 1024;
    int kc   = rem2 >> 8;
    int o    = (rem2 >> 2) & 63;
    int q    = rem2 & 3;
    int i0 = kc * 16 + q * 2;

    const float* wb = w + (((size_t)g * OPG + o) * IPG) * Kt + tap;
    __half v0 = __float2half(wb[(i0 + 0) * Kt]);
    __half v1 = __float2half(wb[(i0 + 1) * Kt]);
    __half v2 = __float2half(wb[(i0 + 8) * Kt]);
    __half v3 = __float2half(wb[(i0 + 9) * Kt]);

    g_wfrag[(size_t)g * 5120 + ((tap * 4 + kc) << 8) + (o * 4 + q)] =
        make_uint2(pack_h2(v0, v1), pack_h2(v2, v3));
}

// ---------------- ptx helpers ----------------
__device__ __forceinline__ uint32_t smem_u32(const void* p) {
    uint32_t a;
    asm("{ .reg .u64 t; cvta.to.shared.u64 t, %1; cvt.u32.u64 %0, t; }" : "=r"(a) : "l"(p));
    return a;
}
__device__ __forceinline__ void ldsm4(uint32_t (&r)[4], uint32_t addr) {
    asm volatile("ldmatrix.sync.aligned.m8n8.x4.shared.b16 {%0,%1,%2,%3}, [%4];"
                 : "=r"(r[0]), "=r"(r[1]), "=r"(r[2]), "=r"(r[3]) : "r"(addr));
}
__device__ __forceinline__ void mma16816(float (&d)[4], const uint32_t (&a)[4],
                                         uint32_t b0, uint32_t b1) {
    asm volatile("mma.sync.aligned.m16n8k16.row.col.f32.f16.f16.f32 "
                 "{%0,%1,%2,%3}, {%4,%5,%6,%7}, {%8,%9}, {%0,%1,%2,%3};"
                 : "+f"(d[0]), "+f"(d[1]), "+f"(d[2]), "+f"(d[3])
                 : "r"(a[0]), "r"(a[1]), "r"(a[2]), "r"(a[3]), "r"(b0), "r"(b1));
}

// ---------------- main kernel ----------------
__global__ __launch_bounds__(NTHR, 2)
void conv_hmma_kernel(const float* __restrict__ inp,
                      const int* __restrict__ pos,
                      float* __restrict__ out) {
    extern __shared__ char smem[];
    const int tid = threadIdx.x;
    const int lam = tid & 31, wid = tid >> 5;
    const int wm = wid & 7, wn = wid >> 3;          // warp grid 8(m) x 2(n)
    const int g = blockIdx.y, b = blockIdx.z;
    const int lt = blockIdx.x * TILE_M;
    const int* posb = pos + (size_t)b * Lr;

    // ---- stage W fragments ----
    {
        const uint4* wsrc = (const uint4*)(g_wfrag + (size_t)g * 5120);
        uint4* wdst = (uint4*)(smem + SM_W);
        #pragma unroll
        for (int it = 0; it < 5; it++)
            wdst[tid + it * NTHR] = wsrc[tid + it * NTHR];
    }

    // ---- stage pos rows [lt-2, lt+258) with OOB sentinel; zero block ----
    {
        int* poss = (int*)(smem + SM_POS);
        if (tid < XROWS) {
            int gl = lt - 2 + tid;
            poss[tid] = (gl >= 0 && gl < Lr) ? __ldg(posb + gl) : -100000;
        }
        if (tid < 8) ((uint4*)(smem + SM_ZERO))[tid] = make_uint4(0, 0, 0, 0);
    }

    // ---- convert X rows to fp16, swizzled 128B rows ----
    for (int e = tid; e < XROWS * 16; e += NTHR) {
        int c4 = e & 15, r = e >> 4;
        int gl = lt - 2 + r;
        float4 v = make_float4(0.f, 0.f, 0.f, 0.f);
        if (gl >= 0 && gl < Lr)
            v = __ldg((const float4*)(inp + ((size_t)b * Lr + gl) * 1024 + g * IPG) + c4);

        __half2 h01 = __float22half2_rn(make_float2(v.x, v.y));
        __half2 h23 = __float22half2_rn(make_float2(v.z, v.w));

        uint32_t off = r * 128 + (((c4 >> 1) ^ (r & 7)) << 4) + (c4 & 1) * 8;
        *(uint2*)(smem + SM_XH + off) =
            make_uint2(*(uint32_t*)&h01, *(uint32_t*)&h23);
    }
    __syncthreads();

    // ---- per-lane mask flags (10 bits: tap x mi) ----
    const uint32_t sb = smem_u32(smem);
    const uint32_t xh_base = sb + SM_XH;
    const uint32_t zeroblk = sb + SM_ZERO;
    const int arow = lam & 15;
    const uint32_t hi16q = (uint32_t)(lam >> 4);     // 0 or 1: col-half selector
    const int row_m0 = wm * 32 + arow;               // A rows for mi=0 / mi=1
    const int row_m1 = row_m0 + 16;
    const int* poss = (const int*)(smem + SM_POS);

    uint32_t flags = 0;
    #pragma unroll
    for (int tap = 0; tap < Kt; tap++) {
        int ls0 = lt + row_m0 + tap - 2;
        int ls1 = lt + row_m1 + tap - 2;
        if (ls0 >= 0 && ls0 < Lr && poss[row_m0 + tap] == poss[row_m0 + 2] + (tap - 2))
            flags |= 1u << (tap * 2);
        if (ls1 >= 0 && ls1 < Lr && poss[row_m1 + tap] == poss[row_m1 + 2] + (tap - 2))
            flags |= 1u << (tap * 2 + 1);
    }

    const uint2* wsm = (const uint2*)(smem + SM_W);
    const int bq = (wn * 32 + (lam >> 2)) * 4 + (lam & 3);

    float facc[2][4][4];
    #pragma unroll
    for (int mi = 0; mi < 2; mi++)
        #pragma unroll
        for (int nj = 0; nj < 4; nj++)
            #pragma unroll
            for (int c = 0; c < 4; c++) facc[mi][nj][c] = 0.f;

    // ---- mainloop: 5 taps x 4 k-steps x 8 MMAs ----
    #pragma unroll
    for (int tap = 0; tap < Kt; tap++) {
        uint32_t base0 = (flags >> (tap * 2)) & 1
                       ? xh_base + (uint32_t)(row_m0 + tap) * 128 : zeroblk;
        uint32_t base1 = (flags >> (tap * 2 + 1)) & 1
                       ? xh_base + (uint32_t)(row_m1 + tap) * 128 : zeroblk;
        uint32_t r7t = (uint32_t)((arow + tap) & 7);

        #pragma unroll
        for (int ks = 0; ks < 4; ks++) {
            uint32_t swz = ((((uint32_t)(ks * 2) + hi16q) ^ r7t) << 4);
            uint32_t a0[4], a1[4];
            ldsm4(a0, base0 + swz);
            ldsm4(a1, base1 + swz);

            #pragma unroll
            for (int nj = 0; nj < 4; nj++) {
                uint2 bb = wsm[(tap * 4 + ks) * 256 + bq + nj * 32];
                mma16816(facc[0][nj], a0, bb.x, bb.y);
                mma16816(facc[1][nj], a1, bb.x, bb.y);
            }
        }
    }

    // ---- epilogue: out[b][l][g][o] ----
    #pragma unroll
    for (int mi = 0; mi < 2; mi++) {
        int row0 = wm * 32 + mi * 16 + (lam >> 2);
        #pragma unroll
        for (int nj = 0; nj < 4; nj++) {
            int col = wn * 32 + nj * 8 + (lam & 3) * 2;
            size_t base = (((size_t)b * Lr + lt + row0) * Gc + g) * OPG + col;
            *(float2*)(out + base) = make_float2(facc[mi][nj][0], facc[mi][nj][1]);
            *(float2*)(out + base + (size_t)8 * Gc * OPG) =
                make_float2(facc[mi][nj][2], facc[mi][nj][3]);
        }
    }
}

extern "C" void kernel_launch(void* const* d_in, const int* in_sizes, int n_in,
                              void* d_out, int out_size) {
    const float* inp = (const float*)d_in[0];   // (4, 4096, 1024) f32
    const int*   pos = (const int*)d_in[1];     // (4, 4096) i32
    const float* w   = (const float*)d_in[2];   // (16, 64, 64, 5) f32
    float* out = (float*)d_out;                 // (4, 4096, 16, 64) f32

    build_wfrag_kernel<<<(Gc * 5120 + 255) / 256, 256>>>(w);

    cudaFuncSetAttribute(conv_hmma_kernel,
                         cudaFuncAttributeMaxDynamicSharedMemorySize, SM_TOTAL);
    dim3 grid(Lr / TILE_M, Gc, Br);   // (16, 16, 4)
    conv_hmma_kernel<<<grid, NTHR, SM_TOTAL>>>(inp, pos, out);
}